// round 5
// baseline (speedup 1.0000x reference)
#include <cuda_runtime.h>

#define DIM 1024
#define NQ 10
#define NL 4
#define WPB 4                         // warps per block (each warp = 2 rows)
#define SWP(i) ((i) + ((i) >> 5))     // stride-33 pad, conflict-free both directions

struct Blob {
    int   npasses;
    int   ident;
    float g[NL][NQ][4];   // [pass][bit][g00,g01,g10,g11]
};

__device__    Blob g_blob;
__constant__  Blob c_blob;
__device__ int g_perm[DIM];

typedef unsigned long long u64;

__device__ __forceinline__ u64 pk2(float lo, float hi) {
    u64 r; asm("mov.b64 %0, {%1, %2};" : "=l"(r) : "f"(lo), "f"(hi)); return r;
}
__device__ __forceinline__ void unpk2(u64 v, float& lo, float& hi) {
    asm("mov.b64 {%0, %1}, %2;" : "=f"(lo), "=f"(hi) : "l"(v));
}
__device__ __forceinline__ u64 fma2(u64 a, u64 b, u64 c) {
    u64 d; asm("fma.rn.f32x2 %0, %1, %2, %3;" : "=l"(d) : "l"(a), "l"(b), "l"(c)); return d;
}
__device__ __forceinline__ u64 mul2(u64 a, u64 b) {
    u64 d; asm("mul.rn.f32x2 %0, %1, %2;" : "=l"(d) : "l"(a), "l"(b)); return d;
}

// ---------------------------------------------------------------------------
// Prep: perm via diagonal shortcut, identity flag, per-bit gates, and 4->1
// layer composition when perm == identity. One block, 1024 threads.
// ---------------------------------------------------------------------------
__global__ void prep_kernel(const float* __restrict__ C,
                            const float* __restrict__ angles) {
    __shared__ int s_ident;
    __shared__ float G[NL][NQ][4];
    int tid = threadIdx.x;
    if (tid == 0) s_ident = 1;
    __syncthreads();

    // permutation-matrix row i: perm[i]=i iff C[i][i] != 0
    {
        int p = tid;
        float d = C[(size_t)tid * DIM + tid];
        if (d == 0.0f) {
            atomicExch(&s_ident, 0);
            const float* row = C + (size_t)tid * DIM;
            for (int j = 0; j < DIM; j++)
                if (row[j] != 0.0f) { p = j; break; }
        }
        g_perm[tid] = p;
    }

    // per-(layer,qubit) gate: G = R(a2/2) @ R(a1/2) @ R(a0/2)
    if (tid < NL * NQ) {
        int l = tid / NQ, q = tid % NQ;
        const float* a = angles + (size_t)(l * NQ + q) * 3;
        float m0 = 1.f, m1 = 0.f, m2 = 0.f, m3 = 1.f;
        #pragma unroll
        for (int k = 0; k < 3; k++) {
            float h = 0.5f * a[k];
            float c = cosf(h), s = sinf(h);
            float n0 = c * m0 - s * m2, n1 = c * m1 - s * m3;
            float n2 = s * m0 + c * m2, n3 = s * m1 + c * m3;
            m0 = n0; m1 = n1; m2 = n2; m3 = n3;
        }
        G[l][q][0] = m0; G[l][q][1] = m1; G[l][q][2] = m2; G[l][q][3] = m3;
    }
    __syncthreads();

    if (s_ident) {
        if (tid < NQ) {   // compose all 4 layers per bit: H_b = G3 G2 G1 G0
            int b = tid, q = 9 - b;
            float m0 = G[0][q][0], m1 = G[0][q][1], m2 = G[0][q][2], m3 = G[0][q][3];
            #pragma unroll
            for (int l = 1; l < NL; l++) {
                float a0 = G[l][q][0], a1 = G[l][q][1], a2 = G[l][q][2], a3 = G[l][q][3];
                float n0 = a0 * m0 + a1 * m2, n1 = a0 * m1 + a1 * m3;
                float n2 = a2 * m0 + a3 * m2, n3 = a2 * m1 + a3 * m3;
                m0 = n0; m1 = n1; m2 = n2; m3 = n3;
            }
            g_blob.g[0][b][0] = m0; g_blob.g[0][b][1] = m1;
            g_blob.g[0][b][2] = m2; g_blob.g[0][b][3] = m3;
        }
        if (tid == 0) { g_blob.npasses = 1; g_blob.ident = 1; }
    } else {
        if (tid < NL * NQ) {
            int l = tid / NQ, b = tid % NQ, q = 9 - b;
            g_blob.g[l][b][0] = G[l][q][0]; g_blob.g[l][b][1] = G[l][q][1];
            g_blob.g[l][b][2] = G[l][q][2]; g_blob.g[l][b][3] = G[l][q][3];
        }
        if (tid == 0) { g_blob.npasses = NL; g_blob.ident = 0; }
    }
}

// ---------------------------------------------------------------------------
// Main: one warp per TWO rows, f32x2 packed butterflies, gates in __constant__.
// Layout A: r[k] = v[lane*32 + k]  (bits 0..4 intra-thread)
// Layout B: r[k] = v[k*32 + lane]  (bits 5..9 intra-thread)
// Fused path: load A -> bits 0-4 -> transpose -> bits 5-9 -> store B (coalesced).
// ---------------------------------------------------------------------------
__global__ __launch_bounds__(32 * WPB, 5)
void qnet_kernel(const float* __restrict__ x, float* __restrict__ out, int nrows) {
    __shared__ u64 buf[WPB][DIM + DIM / 32];
    __shared__ unsigned short sperm[DIM + DIM / 32];   // general path only

    int tid   = threadIdx.x;
    int np    = c_blob.npasses;
    bool fused = (np == 1) && c_blob.ident;

    if (!fused) {
        for (int i = tid; i < DIM; i += blockDim.x)
            sperm[SWP(i)] = (unsigned short)SWP(g_perm[i]);
        __syncthreads();
    }

    int warp = tid >> 5, lane = tid & 31;
    int pairi = blockIdx.x * WPB + warp;
    int row0 = pairi * 2;
    if (row0 >= nrows) return;
    int row1 = (row0 + 1 < nrows) ? row0 + 1 : row0;
    u64* wb = buf[warp];

    // ---- load both rows, layout A, pack {row0, row1} into f32x2 ----
    u64 r[32];
    {
        const float4* p0 = (const float4*)(x + (size_t)row0 * DIM + lane * 32);
        const float4* p1 = (const float4*)(x + (size_t)row1 * DIM + lane * 32);
        #pragma unroll
        for (int k4 = 0; k4 < 8; k4++) {
            float4 v0 = p0[k4], v1 = p1[k4];
            r[k4 * 4 + 0] = pk2(v0.x, v1.x);
            r[k4 * 4 + 1] = pk2(v0.y, v1.y);
            r[k4 * 4 + 2] = pk2(v0.z, v1.z);
            r[k4 * 4 + 3] = pk2(v0.w, v1.w);
        }
    }

    for (int p = 0; p < np; p++) {

        // ---- bits 0..4 (intra-thread, layout A) ----
        #pragma unroll
        for (int b = 0; b < 5; b++) {
            const float* gg = c_blob.g[p][b];
            u64 ga = pk2(gg[0], gg[0]), gb = pk2(gg[1], gg[1]);
            u64 gc = pk2(gg[2], gg[2]), gd = pk2(gg[3], gg[3]);
            int m = 1 << b;
            #pragma unroll
            for (int k0 = 0; k0 < 32; k0++) {
                if (k0 & m) continue;
                int k1 = k0 | m;
                u64 x0 = r[k0], x1 = r[k1];
                r[k0] = fma2(ga, x0, mul2(gb, x1));
                r[k1] = fma2(gc, x0, mul2(gd, x1));
            }
            asm volatile("" ::: "memory");   // keep coeff live ranges per-stage
        }

        // ---- transpose A -> B (conflict-free both directions) ----
        __syncwarp();
        #pragma unroll
        for (int k = 0; k < 32; k++) wb[SWP(lane * 32 + k)] = r[k];
        __syncwarp();
        #pragma unroll
        for (int k = 0; k < 32; k++) r[k] = wb[SWP(k * 32 + lane)];

        // ---- bits 5..9 (intra-thread, layout B) ----
        #pragma unroll
        for (int b = 5; b < 10; b++) {
            const float* gg = c_blob.g[p][b];
            u64 ga = pk2(gg[0], gg[0]), gb = pk2(gg[1], gg[1]);
            u64 gc = pk2(gg[2], gg[2]), gd = pk2(gg[3], gg[3]);
            int m = 1 << (b - 5);
            #pragma unroll
            for (int k0 = 0; k0 < 32; k0++) {
                if (k0 & m) continue;
                int k1 = k0 | m;
                u64 x0 = r[k0], x1 = r[k1];
                r[k0] = fma2(ga, x0, mul2(gb, x1));
                r[k1] = fma2(gc, x0, mul2(gd, x1));
            }
            asm volatile("" ::: "memory");
        }

        if (fused) break;   // store directly from layout B below

        // ---- general path: transpose B -> A with perm folded into gather ----
        __syncwarp();
        #pragma unroll
        for (int k = 0; k < 32; k++) wb[SWP(k * 32 + lane)] = r[k];
        __syncwarp();
        #pragma unroll
        for (int k = 0; k < 32; k++) r[k] = wb[sperm[SWP(lane * 32 + k)]];
    }

    if (fused) {
        // store layout B: element i = k*32+lane, coalesced STG.32 per k
        float* o0 = out + (size_t)row0 * DIM + lane;
        float* o1 = out + (size_t)row1 * DIM + lane;
        #pragma unroll
        for (int k = 0; k < 32; k++) {
            float lo, hi; unpk2(r[k], lo, hi);
            o0[k * 32] = lo;
            o1[k * 32] = hi;
        }
    } else {
        // store layout A: 8x STG.128 per row
        float4* o0 = (float4*)(out + (size_t)row0 * DIM + lane * 32);
        float4* o1 = (float4*)(out + (size_t)row1 * DIM + lane * 32);
        #pragma unroll
        for (int k4 = 0; k4 < 8; k4++) {
            float4 v0, v1;
            unpk2(r[k4 * 4 + 0], v0.x, v1.x);
            unpk2(r[k4 * 4 + 1], v0.y, v1.y);
            unpk2(r[k4 * 4 + 2], v0.z, v1.z);
            unpk2(r[k4 * 4 + 3], v0.w, v1.w);
            o0[k4] = v0; o1[k4] = v1;
        }
    }
}

// ---------------------------------------------------------------------------
extern "C" void kernel_launch(void* const* d_in, const int* in_sizes, int n_in,
                              void* d_out, int out_size) {
    const float* x      = (const float*)d_in[0];   // [BATCH, 1024]
    const float* angles = (const float*)d_in[1];   // [4, 10, 3]
    const float* cnot   = (const float*)d_in[2];   // [1024, 1024]
    float* out = (float*)d_out;

    int nrows = in_sizes[0] / DIM;

    prep_kernel<<<1, DIM>>>(cnot, angles);

    // copy computed blob into __constant__ (D2D async: graph-capturable)
    void* blob_dev = nullptr;
    cudaGetSymbolAddress(&blob_dev, g_blob);
    cudaMemcpyToSymbolAsync(c_blob, blob_dev, sizeof(Blob), 0,
                            cudaMemcpyDeviceToDevice, 0);

    int npairs  = (nrows + 1) / 2;
    int nblocks = (npairs + WPB - 1) / WPB;
    qnet_kernel<<<nblocks, 32 * WPB>>>(x, out, nrows);
}

// round 6
// speedup vs baseline: 1.4789x; 1.4789x over previous
#include <cuda_runtime.h>

#define DIM 1024
#define NQ 10
#define NL 4
#define WPB 4                         // warps per block (each warp = 2 rows)
#define SWP(i) ((i) + ((i) >> 5))     // stride-33 pad, conflict-free both directions

typedef unsigned long long u64;

struct Blob {
    int npasses;
    int ident;
    u64 g[NL][NQ][4];   // packed f32x2 {v,v} duplicates: [pass][bit][g00,g01,g10,g11]
};

__device__   Blob g_blob;
__constant__ Blob c_blob;
__device__ int g_perm[DIM];

__device__ __forceinline__ u64 pk2(float lo, float hi) {
    u64 r; asm("mov.b64 %0, {%1, %2};" : "=l"(r) : "f"(lo), "f"(hi)); return r;
}
__device__ __forceinline__ void unpk2(u64 v, float& lo, float& hi) {
    asm("mov.b64 {%0, %1}, %2;" : "=f"(lo), "=f"(hi) : "l"(v));
}
__device__ __forceinline__ u64 fma2(u64 a, u64 b, u64 c) {
    u64 d; asm("fma.rn.f32x2 %0, %1, %2, %3;" : "=l"(d) : "l"(a), "l"(b), "l"(c)); return d;
}
__device__ __forceinline__ u64 mul2(u64 a, u64 b) {
    u64 d; asm("mul.rn.f32x2 %0, %1, %2;" : "=l"(d) : "l"(a), "l"(b)); return d;
}
// volatile LDS.64: pinned in place (no hoist/CSE), but no global memory barrier,
// so FMA scheduling around it stays free.
__device__ __forceinline__ u64 lds64v(const u64* p) {
    u64 v;
    asm volatile("ld.shared.b64 %0, [%1];"
                 : "=l"(v) : "r"((unsigned)__cvta_generic_to_shared(p)));
    return v;
}

// ---------------------------------------------------------------------------
// Prep: perm via diagonal shortcut, identity flag, per-bit gates (packed u64),
// and 4->1 layer composition when perm == identity. One block, 1024 threads.
// ---------------------------------------------------------------------------
__global__ void prep_kernel(const float* __restrict__ C,
                            const float* __restrict__ angles) {
    __shared__ int s_ident;
    __shared__ float G[NL][NQ][4];
    int tid = threadIdx.x;
    if (tid == 0) s_ident = 1;
    __syncthreads();

    // permutation-matrix row i: perm[i]=i iff C[i][i] != 0
    {
        int p = tid;
        float d = C[(size_t)tid * DIM + tid];
        if (d == 0.0f) {
            atomicExch(&s_ident, 0);
            const float* row = C + (size_t)tid * DIM;
            for (int j = 0; j < DIM; j++)
                if (row[j] != 0.0f) { p = j; break; }
        }
        g_perm[tid] = p;
    }

    // per-(layer,qubit) gate: G = R(a2/2) @ R(a1/2) @ R(a0/2)
    if (tid < NL * NQ) {
        int l = tid / NQ, q = tid % NQ;
        const float* a = angles + (size_t)(l * NQ + q) * 3;
        float m0 = 1.f, m1 = 0.f, m2 = 0.f, m3 = 1.f;
        #pragma unroll
        for (int k = 0; k < 3; k++) {
            float h = 0.5f * a[k];
            float c = cosf(h), s = sinf(h);
            float n0 = c * m0 - s * m2, n1 = c * m1 - s * m3;
            float n2 = s * m0 + c * m2, n3 = s * m1 + c * m3;
            m0 = n0; m1 = n1; m2 = n2; m3 = n3;
        }
        G[l][q][0] = m0; G[l][q][1] = m1; G[l][q][2] = m2; G[l][q][3] = m3;
    }
    __syncthreads();

    if (s_ident) {
        if (tid < NQ) {   // compose all 4 layers per bit: H_b = G3 G2 G1 G0
            int b = tid, q = 9 - b;
            float m0 = G[0][q][0], m1 = G[0][q][1], m2 = G[0][q][2], m3 = G[0][q][3];
            #pragma unroll
            for (int l = 1; l < NL; l++) {
                float a0 = G[l][q][0], a1 = G[l][q][1], a2 = G[l][q][2], a3 = G[l][q][3];
                float n0 = a0 * m0 + a1 * m2, n1 = a0 * m1 + a1 * m3;
                float n2 = a2 * m0 + a3 * m2, n3 = a2 * m1 + a3 * m3;
                m0 = n0; m1 = n1; m2 = n2; m3 = n3;
            }
            g_blob.g[0][b][0] = pk2(m0, m0); g_blob.g[0][b][1] = pk2(m1, m1);
            g_blob.g[0][b][2] = pk2(m2, m2); g_blob.g[0][b][3] = pk2(m3, m3);
        }
        if (tid == 0) { g_blob.npasses = 1; g_blob.ident = 1; }
    } else {
        if (tid < NL * NQ) {
            int l = tid / NQ, b = tid % NQ, q = 9 - b;
            g_blob.g[l][b][0] = pk2(G[l][q][0], G[l][q][0]);
            g_blob.g[l][b][1] = pk2(G[l][q][1], G[l][q][1]);
            g_blob.g[l][b][2] = pk2(G[l][q][2], G[l][q][2]);
            g_blob.g[l][b][3] = pk2(G[l][q][3], G[l][q][3]);
        }
        if (tid == 0) { g_blob.npasses = NL; g_blob.ident = 0; }
    }
}

// ---------------------------------------------------------------------------
// Main: one warp per TWO rows, f32x2 packed butterflies.
// Coefficients live in smem (pre-packed u64), fetched per-stage via volatile
// LDS.64 so ptxas cannot hoist them into ~80 registers.
// Layout A: r[k] = v[lane*32 + k]  (bits 0..4 intra-thread)
// Layout B: r[k] = v[k*32 + lane]  (bits 5..9 intra-thread)
// Fused path: load A -> bits 0-4 -> transpose -> bits 5-9 -> store B (coalesced).
// ---------------------------------------------------------------------------
__global__ __launch_bounds__(32 * WPB)
void qnet_kernel(const float* __restrict__ x, float* __restrict__ out, int nrows) {
    __shared__ u64 buf[WPB][DIM + DIM / 32];
    __shared__ u64 scoef[NL][NQ][4];
    __shared__ unsigned short sperm[DIM + DIM / 32];   // general path only

    int tid   = threadIdx.x;
    int np    = c_blob.npasses;
    bool fused = (np == 1) && c_blob.ident;

    if (tid < NL * NQ * 4)
        ((u64*)scoef)[tid] = ((const u64*)c_blob.g)[tid];
    if (!fused) {
        for (int i = tid; i < DIM; i += blockDim.x)
            sperm[SWP(i)] = (unsigned short)SWP(g_perm[i]);
    }
    __syncthreads();

    int warp = tid >> 5, lane = tid & 31;
    int pairi = blockIdx.x * WPB + warp;
    int row0 = pairi * 2;
    if (row0 >= nrows) return;
    int row1 = (row0 + 1 < nrows) ? row0 + 1 : row0;
    u64* wb = buf[warp];

    // ---- load both rows, layout A, pack {row0, row1} into f32x2 ----
    u64 r[32];
    {
        const float4* p0 = (const float4*)(x + (size_t)row0 * DIM + lane * 32);
        const float4* p1 = (const float4*)(x + (size_t)row1 * DIM + lane * 32);
        #pragma unroll
        for (int k4 = 0; k4 < 8; k4++) {
            float4 v0 = p0[k4], v1 = p1[k4];
            r[k4 * 4 + 0] = pk2(v0.x, v1.x);
            r[k4 * 4 + 1] = pk2(v0.y, v1.y);
            r[k4 * 4 + 2] = pk2(v0.z, v1.z);
            r[k4 * 4 + 3] = pk2(v0.w, v1.w);
        }
    }

    for (int p = 0; p < np; p++) {

        // ---- bits 0..4 (intra-thread, layout A) ----
        #pragma unroll
        for (int b = 0; b < 5; b++) {
            const u64* gg = scoef[p][b];
            u64 ga = lds64v(gg + 0), gb = lds64v(gg + 1);
            u64 gc = lds64v(gg + 2), gd = lds64v(gg + 3);
            int m = 1 << b;
            #pragma unroll
            for (int k0 = 0; k0 < 32; k0++) {
                if (k0 & m) continue;
                int k1 = k0 | m;
                u64 x0 = r[k0], x1 = r[k1];
                r[k0] = fma2(ga, x0, mul2(gb, x1));
                r[k1] = fma2(gc, x0, mul2(gd, x1));
            }
        }

        // ---- transpose A -> B (conflict-free both directions) ----
        __syncwarp();
        #pragma unroll
        for (int k = 0; k < 32; k++) wb[SWP(lane * 32 + k)] = r[k];
        __syncwarp();
        #pragma unroll
        for (int k = 0; k < 32; k++) r[k] = wb[SWP(k * 32 + lane)];

        // ---- bits 5..9 (intra-thread, layout B) ----
        #pragma unroll
        for (int b = 5; b < 10; b++) {
            const u64* gg = scoef[p][b];
            u64 ga = lds64v(gg + 0), gb = lds64v(gg + 1);
            u64 gc = lds64v(gg + 2), gd = lds64v(gg + 3);
            int m = 1 << (b - 5);
            #pragma unroll
            for (int k0 = 0; k0 < 32; k0++) {
                if (k0 & m) continue;
                int k1 = k0 | m;
                u64 x0 = r[k0], x1 = r[k1];
                r[k0] = fma2(ga, x0, mul2(gb, x1));
                r[k1] = fma2(gc, x0, mul2(gd, x1));
            }
        }

        if (fused) break;   // store directly from layout B below

        // ---- general path: transpose B -> A with perm folded into gather ----
        __syncwarp();
        #pragma unroll
        for (int k = 0; k < 32; k++) wb[SWP(k * 32 + lane)] = r[k];
        __syncwarp();
        #pragma unroll
        for (int k = 0; k < 32; k++) r[k] = wb[sperm[SWP(lane * 32 + k)]];
    }

    if (fused) {
        // store layout B: element i = k*32+lane, coalesced STG.32 per k
        float* o0 = out + (size_t)row0 * DIM + lane;
        float* o1 = out + (size_t)row1 * DIM + lane;
        #pragma unroll
        for (int k = 0; k < 32; k++) {
            float lo, hi; unpk2(r[k], lo, hi);
            o0[k * 32] = lo;
            o1[k * 32] = hi;
        }
    } else {
        // store layout A: 8x STG.128 per row
        float4* o0 = (float4*)(out + (size_t)row0 * DIM + lane * 32);
        float4* o1 = (float4*)(out + (size_t)row1 * DIM + lane * 32);
        #pragma unroll
        for (int k4 = 0; k4 < 8; k4++) {
            float4 v0, v1;
            unpk2(r[k4 * 4 + 0], v0.x, v1.x);
            unpk2(r[k4 * 4 + 1], v0.y, v1.y);
            unpk2(r[k4 * 4 + 2], v0.z, v1.z);
            unpk2(r[k4 * 4 + 3], v0.w, v1.w);
            o0[k4] = v0; o1[k4] = v1;
        }
    }
}

// ---------------------------------------------------------------------------
extern "C" void kernel_launch(void* const* d_in, const int* in_sizes, int n_in,
                              void* d_out, int out_size) {
    const float* x      = (const float*)d_in[0];   // [BATCH, 1024]
    const float* angles = (const float*)d_in[1];   // [4, 10, 3]
    const float* cnot   = (const float*)d_in[2];   // [1024, 1024]
    float* out = (float*)d_out;

    int nrows = in_sizes[0] / DIM;

    prep_kernel<<<1, DIM>>>(cnot, angles);

    // copy computed blob into __constant__ (D2D async: graph-capturable)
    void* blob_dev = nullptr;
    cudaGetSymbolAddress(&blob_dev, g_blob);
    cudaMemcpyToSymbolAsync(c_blob, blob_dev, sizeof(Blob), 0,
                            cudaMemcpyDeviceToDevice, 0);

    int npairs  = (nrows + 1) / 2;
    int nblocks = (npairs + WPB - 1) / WPB;
    qnet_kernel<<<nblocks, 32 * WPB>>>(x, out, nrows);
}